// round 17
// baseline (speedup 1.0000x reference)
#include <cuda_runtime.h>
#include <cstdint>

#define TT 2048
#define CH 16
#define NCH (TT / CH)      // 128 chunks
#define PAD 33
#define NEP (NCH + 5)

__device__ __forceinline__ float ex2_ap (float x){ float r; asm("ex2.approx.f32 %0, %1;"   : "=f"(r) : "f"(x)); return r; }
__device__ __forceinline__ float rcp_ap (float x){ float r; asm("rcp.approx.f32 %0, %1;"   : "=f"(r) : "f"(x)); return r; }
__device__ __forceinline__ float sqrt_ap(float x){ float r; asm("sqrt.approx.f32 %0, %1;"  : "=f"(r) : "f"(x)); return r; }
__device__ __forceinline__ float rsq_ap (float x){ float r; asm("rsqrt.approx.f32 %0, %1;" : "=f"(r) : "f"(x)); return r; }
__device__ __forceinline__ float clampf(float x, float lo, float hi){ return fminf(fmaxf(x, lo), hi); }
__device__ __forceinline__ float relu(float x){ return fmaxf(x, 0.f); }

// dynamic smem layout (bytes)
#define F2PLANE (CH * PAD * 8)
#define F4PLANE (CH * PAD * 16)
#define OFF_P1   0                          // f4 x2 : SMS1c, infil, xrr      (W1 -> W2, d=1)
#define OFF_P3P  (OFF_P1  + 2 * F4PLANE)    // f4 x4 : BAS, crs, krR, RSov    (W3 -> W4 d=1, W5 d=2)
#define OFF_P0A  (OFF_P3P + 4 * F4PLANE)    // f2 x4 : INR, POT               (W0 -> W1 d=1, W2 d=2)
#define OFF_P0B  (OFF_P0A + 4 * F2PLANE)    // f2 x8 : RSmax, Area            (W0 -> W3 d=3, W4 d=4, W5 d=5)
#define OFF_P2   (OFF_P0B + 8 * F2PLANE)    // f2 x4 : U, RECn                (W2 -> W3 d=1, W4 d=2, W5 d=3)
#define OFF_P4   (OFF_P2  + 4 * F2PLANE)    // f2 x2 : RSn, x6                (W4 -> W5, d=1)
#define OFF_FIN1 (OFF_P4  + 2 * F2PLANE)
#define OFF_FIN2 (OFF_FIN1 + 128)
#define OFF_RS0  (OFF_FIN2 + 128)
#define SMEM_TOTAL (OFF_RS0 + 128)

struct Consts {
  float insc, Sc, Sinv, kexp, lCc, sub, crak, rk, lg, kr, ls;
  float tenSinv, a2, b2;
};

// Full pass-2 Q for t==0: rolled SMS/GW = FINAL states, RS = outs[b,0,2]
__device__ __forceinline__ float q_final(float4 v, float SMS1r, float GW1r, float RSr, const Consts& c)
{
  float Prec = v.x, PET = v.y, RSmax = v.z, Area = v.w;
  float INTC = fminf(fminf(c.insc, PET), Prec);
  float INR  = Prec - INTC;
  float SMS1c = fmaxf(fminf(SMS1r, c.Sc), 0.f);
  float infil = ex2_ap(fmaf(c.kexp, SMS1c, c.lCc));
  float RMO = fminf(INR, infil);
  float IRUN = INR - RMO;
  float ratio = SMS1c * c.Sinv;
  float SRUN = c.sub * ratio * RMO;
  float BAS = c.rk * relu(GW1r);
  float inflow = (IRUN + SRUN + BAS) * Area;
  float x5 = RSr + inflow - RSmax;
  float Qor = relu(x5);
  float r = relu(RSr) * rcp_ap(RSmax);
  float pw = r * sqrt_ap(r);
  float Qir = (x5 > 0.f) ? (c.kr * RSmax) : (c.kr * RSr * pw);
  float drarg = (SRUN + IRUN) * (1.f - Area) + Qir + Qor - c.ls;
  float DR = relu(drarg);
  float GD = BAS * (1.f - Area);
  return relu(DR + GD);
}

__global__ void __launch_bounds__(192, 1)
hirnn_kernel(const float4* __restrict__ xin_all,
             const float* __restrict__ pINSC, const float* __restrict__ pCOEFF,
             const float* __restrict__ pSQ,   const float* __restrict__ pSMSC,
             const float* __restrict__ pSUB,  const float* __restrict__ pCRAK,
             const float* __restrict__ pRecK, const float* __restrict__ pKr,
             const float* __restrict__ pLG,   const float* __restrict__ pLS,
             float* __restrict__ out, int B)
{
  const int lane = threadIdx.x & 31;
  const int warp = threadIdx.x >> 5;
  const int seq  = blockIdx.x * 32 + lane;

  extern __shared__ unsigned char dyn[];
  typedef float2 P2CH[CH][PAD];
  typedef float4 P4CH[CH][PAD];
  P4CH* p1  = (P4CH*)(dyn + OFF_P1);    // [2]: SMS1c, infil, xrr
  P4CH* p3p = (P4CH*)(dyn + OFF_P3P);   // [4]: BAS, crs, krR, RSov
  P2CH* p0a = (P2CH*)(dyn + OFF_P0A);   // [4]: INR, POT
  P2CH* p0b = (P2CH*)(dyn + OFF_P0B);   // [8]: RSmax, Area
  P2CH* p2  = (P2CH*)(dyn + OFF_P2);    // [4]: U, RECn
  P2CH* p4  = (P2CH*)(dyn + OFF_P4);    // [2]: RSn, x6
  float* fin1 = (float*)(dyn + OFF_FIN1);
  float* fin2 = (float*)(dyn + OFF_FIN2);
  float* rs0s = (float*)(dyn + OFF_RS0);

  Consts c;
  c.insc = clampf(pINSC[0] * 5.f, 0.5f, 5.f);
  float Cc = clampf(pCOEFF[0] * 400.f, 50.f, 400.f);
  float qv = clampf(pSQ[0] * 6.f, 0.f, 6.f);
  c.Sc   = clampf(pSMSC[0] * 500.f, 50.f, 500.f);
  c.Sinv = 1.f / c.Sc;
  c.kexp = -qv * c.Sinv * 1.4426950408889634f;   // Cc*exp(-q*s/S) == exp2(kexp*s + lCc)
  c.lCc  = log2f(Cc);
  c.sub  = clampf(pSUB[0], 0.f, 1.f);
  c.crak = clampf(pCRAK[0], 0.f, 1.f);
  c.rk   = clampf(pRecK[0] * 0.3f, 0.003f, 0.3f);
  c.lg   = clampf(pLG[0] * 0.1f, 0.001f, 0.1f);
  c.kr   = clampf(pKr[0] * 0.1f, 0.01f, 0.1f);
  c.ls   = clampf(pLS[0] * 10.f, 0.01f, 10.f);
  c.tenSinv = 10.f * c.Sinv;
  c.a2 = c.sub + c.crak;
  c.b2 = c.sub * c.crak;

  const float4* __restrict__ xin = xin_all + (size_t)seq * TT;
  float* __restrict__ op = out + (size_t)seq * TT;

  if (warp == 0) {
    // ---------- stage 0 (chunk e): load + interception ----------
    float4 bA[CH], bB[CH];
#pragma unroll
    for (int i = 0; i < CH; i++) bA[i] = xin[i];
    for (int e = 0; e < NEP; ++e) {
      if (e < NCH) {
        const int sa = e & 3, sb = e & 7;
        if ((e & 1) == 0) {
          if (e + 1 < NCH) {
#pragma unroll
            for (int i = 0; i < CH; i++) bB[i] = xin[(e + 1) * CH + i];
          }
#pragma unroll
          for (int i = 0; i < CH; i++) {
            float Prec = bA[i].x, PET = bA[i].y;
            float INTC = fminf(fminf(c.insc, PET), Prec);
            p0a[sa][i][lane] = make_float2(Prec - INTC, PET - INTC);
            p0b[sb][i][lane] = make_float2(bA[i].z, bA[i].w);
          }
        } else {
          if (e + 1 < NCH) {
#pragma unroll
            for (int i = 0; i < CH; i++) bA[i] = xin[(e + 1) * CH + i];
          }
#pragma unroll
          for (int i = 0; i < CH; i++) {
            float Prec = bB[i].x, PET = bB[i].y;
            float INTC = fminf(fminf(c.insc, PET), Prec);
            p0a[sa][i][lane] = make_float2(Prec - INTC, PET - INTC);
            p0b[sb][i][lane] = make_float2(bB[i].z, bB[i].w);
          }
        }
      }
      __syncthreads();
    }
  } else if (warp == 1) {
    // ---------- stage 1 (chunk e-1): SMS recurrence only ----------
    float S = 0.f;
    for (int e = 0; e < NEP; ++e) {
      const int k = e - 1;
      if (k >= 0 && k < NCH) {
        const int s0 = k & 3, sd = k & 1;
        float2 io[CH];
#pragma unroll
        for (int i = 0; i < CH; i++) io[i] = p0a[s0][i][lane];
#pragma unroll
        for (int i = 0; i < CH; i++) {
          float INR = io[i].x, POT = io[i].y;
          float SMS1c = fminf(S, c.Sc);                 // >=0 invariant
          float infil = ex2_ap(fmaf(c.kexp, SMS1c, c.lCc));
          float ratio = SMS1c * c.Sinv;
          float ETS  = fminf(POT, SMS1c * c.tenSinv);
          float base = SMS1c - ETS;
          float m = fmaf(fmaf(c.b2, ratio, -c.a2), ratio, 1.f);  // (1-sr)(1-cr)
          float w = fmaf(m, INR,   base);
          float z = fmaf(m, infil, base);
          float SMSn = fminf(w, z);                     // base + m*min(INR,infil)
          float xrr  = relu(SMSn - c.Sc);
          p1[sd][i][lane] = make_float4(SMS1c, infil, xrr, 0.f);
          S = SMSn;
        }
        if (k == NCH - 1) fin1[lane] = S;
      }
      __syncthreads();
    }
  } else if (warp == 2) {
    // ---------- stage 2 (chunk e-2): U / RECn reconstruction (NO recurrence) ----------
    for (int e = 0; e < NEP; ++e) {
      const int k = e - 2;
      if (k >= 0 && k < NCH) {
        const int s0 = k & 3, s1 = k & 1, sd = k & 3;
#pragma unroll
        for (int h = 0; h < 2; ++h) {
          float2 io[8]; float4 sp[8];
#pragma unroll
          for (int j = 0; j < 8; ++j) {
            int idx = h * 8 + j;
            io[j] = p0a[s0][idx][lane];
            sp[j] = p1[s1][idx][lane];
          }
#pragma unroll
          for (int j = 0; j < 8; ++j) {
            int idx = h * 8 + j;
            float INR = io[j].x;
            float SMS1c = sp[j].x, infil = sp[j].y, xrr = sp[j].z;
            float ratio = SMS1c * c.Sinv;
            float msr  = fmaf(-c.sub, ratio, 1.f);
            float mcr  = (c.crak * ratio) * msr;
            float RMO  = fminf(INR, infil);
            float U    = fmaf(-msr, RMO, INR);          // IRUN + SRUN
            float RECn = fmaf(mcr, RMO, xrr);           // REC + relu(xr)
            p2[sd][idx][lane] = make_float2(U, RECn);
          }
        }
      }
      __syncthreads();
    }
  } else if (warp == 3) {
    // ---------- stage 3 (chunk e-3): GW recurrence + RSmax consts ----------
    float G = 0.f;
    for (int e = 0; e < NEP; ++e) {
      const int k = e - 3;
      if (k >= 0 && k < NCH) {
        const int s0 = k & 7, s2 = k & 3, sd = k & 3;
#pragma unroll
        for (int h = 0; h < 2; ++h) {
          float rms[8], rcn[8];
#pragma unroll
          for (int j = 0; j < 8; ++j) {
            int idx = h * 8 + j;
            rms[j] = p0b[s0][idx][lane].x;
            rcn[j] = p2[s2][idx][lane].y;
          }
#pragma unroll
          for (int j = 0; j < 8; ++j) {
            int idx = h * 8 + j;
            float RSmax = rms[j];
            float u    = rsq_ap(RSmax);
            float crs  = c.kr * ((u * u) * u);          // kr * RSmax^-1.5
            float krR  = c.kr * RSmax;
            float RSov = RSmax - krR;
            float BAS  = c.rk * relu(G);
            float GWn  = ((G - c.lg) + rcn[j]) - BAS;
            p3p[sd][idx][lane] = make_float4(BAS, crs, krR, RSov);
            G = GWn;
          }
        }
        if (k == NCH - 1) fin2[lane] = G;
      }
      __syncthreads();
    }
  } else if (warp == 4) {
    // ---------- stage 4 (chunk e-4): bare RS recurrence ----------
    float R = 0.f, sqR = 0.f;
    for (int e = 0; e < NEP; ++e) {
      const int k = e - 4;
      if (k >= 0 && k < NCH) {
        const int s0 = k & 7, s2 = k & 3, s3 = k & 3, sd = k & 1;
#pragma unroll
        for (int h = 0; h < 2; ++h) {
          float2 rb[8]; float Ux[8]; float4 qa[8];
#pragma unroll
          for (int j = 0; j < 8; ++j) {
            int idx = h * 8 + j;
            rb[j] = p0b[s0][idx][lane];
            Ux[j] = p2[s2][idx][lane].x;
            qa[j] = p3p[s3][idx][lane];
          }
#pragma unroll
          for (int j = 0; j < 8; ++j) {
            int idx = h * 8 + j;
            float RSmax = rb[j].x, Area = rb[j].y;
            float inflow = (Ux[j] + qa[j].x) * Area;
            float Rpi = R + inflow;
            float x5  = Rpi - RSmax;
            float t1  = (qa[j].y * sqR) * R;            // kr * R^1.5 / RSmax^1.5
            float RSn_no = fmaf(-t1, R, Rpi);
            float RSn = (x5 > 0.f) ? qa[j].w : RSn_no;
            float sqn = sqrt_ap(RSn);
            float x6  = (RSn + inflow) - RSmax;
            p4[sd][idx][lane] = make_float2(RSn, x6);
            if (k == 0 && idx == 0) rs0s[lane] = RSn;
            R = RSn; sqR = sqn;
          }
        }
      }
      __syncthreads();
    }
  } else {
    // ---------- stage 5 (chunk e-5): Q tail + stores ----------
    for (int e = 0; e < NEP; ++e) {
      const int k = e - 5;
      if (k >= 0 && k < NCH) {
        const int s0 = k & 7, s2 = k & 3, s3 = k & 3, s4 = k & 1;
#pragma unroll
        for (int h = 0; h < 2; ++h) {
          float2 r4[8]; float4 qa[8]; float Ux[8], Ar[8];
#pragma unroll
          for (int j = 0; j < 8; ++j) {
            int idx = h * 8 + j;
            r4[j] = p4[s4][idx][lane];
            qa[j] = p3p[s3][idx][lane];
            Ux[j] = p2[s2][idx][lane].x;
            Ar[j] = p0b[s0][idx][lane].y;
          }
          float qb0 = 0.f, qb1 = 0.f, qb2 = 0.f;
#pragma unroll
          for (int j = 0; j < 8; ++j) {
            float RSn = r4[j].x, x6 = r4[j].y;
            float BAS = qa[j].x, crs = qa[j].y, krR = qa[j].z;
            float onemA = 1.f - Ar[j];
            float sqn = sqrt_ap(RSn);
            float Qor2 = relu(x6);
            float qno = (crs * RSn) * (RSn * sqn);      // kr*RSn*(RSn/RSmax)^1.5
            float Qir2 = (x6 > 0.f) ? krR : qno;
            float ssum = (Qir2 + Qor2) - c.ls;
            float drarg = fmaf(Ux[j], onemA, ssum);
            float Q = relu(relu(drarg) + BAS * onemA);
            int ii = j & 3;
            if      (ii == 0) qb0 = Q;
            else if (ii == 1) qb1 = Q;
            else if (ii == 2) qb2 = Q;
            else *reinterpret_cast<float4*>(op + k * CH + h * 8 + j - 3) =
                   make_float4(qb0, qb1, qb2, Q);
          }
        }
      }
      __syncthreads();
    }
    // Q[b,0]: jnp.roll wrap -> SMS1/GW1 = FINAL states; RS = outs[b,0,2]
    float4 f = xin[0];
    op[0] = q_final(f, fin1[lane], fin2[lane], rs0s[lane], c);
  }
}

extern "C" void kernel_launch(void* const* d_in, const int* in_sizes, int n_in,
                              void* d_out, int out_size) {
  const float4* xin = (const float4*)d_in[0];
  int B = out_size / TT;
  int grid = B / 32;
  static int attr_set = 0;
  if (!attr_set) {
    cudaFuncSetAttribute(hirnn_kernel, cudaFuncAttributeMaxDynamicSharedMemorySize, SMEM_TOTAL);
    attr_set = 1;
  }
  hirnn_kernel<<<grid, 192, SMEM_TOTAL>>>(xin,
      (const float*)d_in[1], (const float*)d_in[2], (const float*)d_in[3],
      (const float*)d_in[4], (const float*)d_in[5], (const float*)d_in[6],
      (const float*)d_in[7], (const float*)d_in[8], (const float*)d_in[9],
      (const float*)d_in[10],
      (float*)d_out, B);
}